// round 1
// baseline (speedup 1.0000x reference)
#include <cuda_runtime.h>
#include <math.h>

#define NN   100000
#define EEDG 1600000
#define HIDW 64
#define OUTW 40
#define BN_EPS 1e-5f

// Scratch (static device globals; allocation is forbidden)
__device__ __align__(16) float g_agg [NN * HIDW];
__device__ __align__(16) float g_bufA[NN * HIDW];
__device__ __align__(16) float g_bufB[NN * HIDW];
__device__ float g_stats1[2 * HIDW];
__device__ float g_stats2[2 * HIDW];

// ---------------------------------------------------------------------------
// Scatter: agg[dst] += h[src], 16 threads per edge, float4 gather + red.v4
// ---------------------------------------------------------------------------
__global__ __launch_bounds__(256) void scatter_kernel(
    const float* __restrict__ h, const int* __restrict__ src,
    const int* __restrict__ dst, float* __restrict__ agg, int nE)
{
    int t = blockIdx.x * 256 + threadIdx.x;
    int e = t >> 4;
    if (e >= nE) return;
    int c = t & 15;
    int s = __ldg(src + e);
    int d = __ldg(dst + e);
    float4 v = __ldg((const float4*)h + (size_t)s * 16 + c);
    float* p = agg + (size_t)d * 64 + c * 4;
    asm volatile("red.global.add.v4.f32 [%0], {%1,%2,%3,%4};"
                 :: "l"(p), "f"(v.x), "f"(v.y), "f"(v.z), "f"(v.w)
                 : "memory");
}

// ---------------------------------------------------------------------------
// mm1: r = h + agg ; y = r @ W1 + b1     (64 -> 64)
// ---------------------------------------------------------------------------
__global__ __launch_bounds__(256) void mm1_kernel(
    const float* __restrict__ h, const float* __restrict__ agg,
    const float* __restrict__ W, const float* __restrict__ bias,
    float* __restrict__ y, int n)
{
    __shared__ float Ws[64 * 64];
    for (int i = threadIdx.x; i < 64 * 64; i += 256) Ws[i] = W[i];
    __syncthreads();
    int node = blockIdx.x * 256 + threadIdx.x;
    if (node >= n) return;

    float r[64];
    const float4* h4 = (const float4*)h   + (size_t)node * 16;
    const float4* a4 = (const float4*)agg + (size_t)node * 16;
#pragma unroll
    for (int k4 = 0; k4 < 16; k4++) {
        float4 hv = __ldg(h4 + k4);
        float4 av = __ldg(a4 + k4);
        r[4*k4+0] = hv.x + av.x; r[4*k4+1] = hv.y + av.y;
        r[4*k4+2] = hv.z + av.z; r[4*k4+3] = hv.w + av.w;
    }
    float4* yo = (float4*)y + (size_t)node * 16;
    const float4* b4 = (const float4*)bias;
    const float4* W4 = (const float4*)Ws;
    for (int j4 = 0; j4 < 16; j4++) {
        float4 acc = b4[j4];
#pragma unroll
        for (int k = 0; k < 64; k++) {
            float4 w = W4[k * 16 + j4];
            acc.x = fmaf(r[k], w.x, acc.x);
            acc.y = fmaf(r[k], w.y, acc.y);
            acc.z = fmaf(r[k], w.z, acc.z);
            acc.w = fmaf(r[k], w.w, acc.w);
        }
        yo[j4] = acc;
    }
}

// ---------------------------------------------------------------------------
// Column stats: stats[0:64] += colsum, stats[64:128] += colsumsq  (64 cols)
// ---------------------------------------------------------------------------
__global__ __launch_bounds__(256) void colstats_kernel(
    const float* __restrict__ v, float* __restrict__ stats, long total)
{
    float s = 0.f, sq = 0.f;
    long stride = (long)gridDim.x * 256;
    for (long i = (long)blockIdx.x * 256 + threadIdx.x; i < total; i += stride) {
        float x = v[i];
        s += x; sq += x * x;
    }
    __shared__ float sh[512];
    sh[threadIdx.x] = s;
    sh[256 + threadIdx.x] = sq;
    __syncthreads();
    if (threadIdx.x < 64) {
        float ts = 0.f, tq = 0.f;
#pragma unroll
        for (int r = 0; r < 256; r += 64) {
            ts += sh[threadIdx.x + r];
            tq += sh[256 + threadIdx.x + r];
        }
        atomicAdd(&stats[threadIdx.x], ts);
        atomicAdd(&stats[64 + threadIdx.x], tq);
    }
}

// ---------------------------------------------------------------------------
// mm2 (mid layers): h1 = relu(BN(y)) ; z = h1 @ W2 + b2 ; a = relu(z)
// ---------------------------------------------------------------------------
__global__ __launch_bounds__(256) void mm2_mid_kernel(
    const float* __restrict__ y, const float* __restrict__ stats,
    const float* __restrict__ g, const float* __restrict__ bt,
    const float* __restrict__ W, const float* __restrict__ bias,
    float* __restrict__ a_out, int n, float invN)
{
    __shared__ float Ws[64 * 64];
    __shared__ float alpha[64], beta[64];
    for (int i = threadIdx.x; i < 64 * 64; i += 256) Ws[i] = W[i];
    if (threadIdx.x < 64) {
        int c = threadIdx.x;
        float mu  = stats[c] * invN;
        float var = stats[64 + c] * invN - mu * mu;
        float al  = g[c] * rsqrtf(var + BN_EPS);
        alpha[c] = al;
        beta[c]  = bt[c] - al * mu;
    }
    __syncthreads();
    int node = blockIdx.x * 256 + threadIdx.x;
    if (node >= n) return;

    float r[64];
    const float4* y4 = (const float4*)y + (size_t)node * 16;
#pragma unroll
    for (int k4 = 0; k4 < 16; k4++) {
        float4 v = __ldg(y4 + k4);
        int k = 4 * k4;
        r[k+0] = fmaxf(fmaf(alpha[k+0], v.x, beta[k+0]), 0.f);
        r[k+1] = fmaxf(fmaf(alpha[k+1], v.y, beta[k+1]), 0.f);
        r[k+2] = fmaxf(fmaf(alpha[k+2], v.z, beta[k+2]), 0.f);
        r[k+3] = fmaxf(fmaf(alpha[k+3], v.w, beta[k+3]), 0.f);
    }
    float4* ao = (float4*)a_out + (size_t)node * 16;
    const float4* b4 = (const float4*)bias;
    const float4* W4 = (const float4*)Ws;
    for (int j4 = 0; j4 < 16; j4++) {
        float4 acc = b4[j4];
#pragma unroll
        for (int k = 0; k < 64; k++) {
            float4 w = W4[k * 16 + j4];
            acc.x = fmaf(r[k], w.x, acc.x);
            acc.y = fmaf(r[k], w.y, acc.y);
            acc.z = fmaf(r[k], w.z, acc.z);
            acc.w = fmaf(r[k], w.w, acc.w);
        }
        acc.x = fmaxf(acc.x, 0.f); acc.y = fmaxf(acc.y, 0.f);
        acc.z = fmaxf(acc.z, 0.f); acc.w = fmaxf(acc.w, 0.f);
        ao[j4] = acc;
    }
}

// ---------------------------------------------------------------------------
// mm2 final: h1 = relu(BN(y)) ; z = h1 @ W2 + b2 (64->40) ; out = log_softmax(z)
// ---------------------------------------------------------------------------
__global__ __launch_bounds__(128) void mm2_final_kernel(
    const float* __restrict__ y, const float* __restrict__ stats,
    const float* __restrict__ g, const float* __restrict__ bt,
    const float* __restrict__ W, const float* __restrict__ bias,
    float* __restrict__ out, int n, float invN)
{
    __shared__ float Ws[64 * 40];
    __shared__ float alpha[64], beta[64];
    for (int i = threadIdx.x; i < 64 * 40; i += 128) Ws[i] = W[i];
    if (threadIdx.x < 64) {
        int c = threadIdx.x;
        float mu  = stats[c] * invN;
        float var = stats[64 + c] * invN - mu * mu;
        float al  = g[c] * rsqrtf(var + BN_EPS);
        alpha[c] = al;
        beta[c]  = bt[c] - al * mu;
    }
    __syncthreads();
    int node = blockIdx.x * 128 + threadIdx.x;
    if (node >= n) return;

    float r[64];
    const float4* y4 = (const float4*)y + (size_t)node * 16;
#pragma unroll
    for (int k4 = 0; k4 < 16; k4++) {
        float4 v = __ldg(y4 + k4);
        int k = 4 * k4;
        r[k+0] = fmaxf(fmaf(alpha[k+0], v.x, beta[k+0]), 0.f);
        r[k+1] = fmaxf(fmaf(alpha[k+1], v.y, beta[k+1]), 0.f);
        r[k+2] = fmaxf(fmaf(alpha[k+2], v.z, beta[k+2]), 0.f);
        r[k+3] = fmaxf(fmaf(alpha[k+3], v.w, beta[k+3]), 0.f);
    }
    float z[40];
    const float4* b4 = (const float4*)bias;
    const float4* W4 = (const float4*)Ws;
    for (int j4 = 0; j4 < 10; j4++) {
        float4 acc = b4[j4];
#pragma unroll
        for (int k = 0; k < 64; k++) {
            float4 w = W4[k * 10 + j4];
            acc.x = fmaf(r[k], w.x, acc.x);
            acc.y = fmaf(r[k], w.y, acc.y);
            acc.z = fmaf(r[k], w.z, acc.z);
            acc.w = fmaf(r[k], w.w, acc.w);
        }
        z[4*j4+0] = acc.x; z[4*j4+1] = acc.y;
        z[4*j4+2] = acc.z; z[4*j4+3] = acc.w;
    }
    float m = z[0];
#pragma unroll
    for (int j = 1; j < 40; j++) m = fmaxf(m, z[j]);
    float s = 0.f;
#pragma unroll
    for (int j = 0; j < 40; j++) s += expf(z[j] - m);
    float lse = m + logf(s);
    float4* o4 = (float4*)out + (size_t)node * 10;
    for (int j4 = 0; j4 < 10; j4++) {
        float4 v;
        v.x = z[4*j4+0] - lse; v.y = z[4*j4+1] - lse;
        v.z = z[4*j4+2] - lse; v.w = z[4*j4+3] - lse;
        o4[j4] = v;
    }
}

// ---------------------------------------------------------------------------
// Outer BN apply (in place): a = g*(a-mu)*rsqrt(var+eps) + b   (float4)
// ---------------------------------------------------------------------------
__global__ __launch_bounds__(256) void bn_apply_kernel(
    float* __restrict__ a, const float* __restrict__ stats,
    const float* __restrict__ g, const float* __restrict__ b,
    int n, float invN)
{
    int i = blockIdx.x * 256 + threadIdx.x;
    if (i >= n * 16) return;
    int c = (i & 15) * 4;
    float4 v = ((float4*)a)[i];
    float al, be, mu, var;
#define BN_COMP(comp, cc)                                              \
    mu  = __ldg(stats + (cc)) * invN;                                  \
    var = __ldg(stats + 64 + (cc)) * invN - mu * mu;                   \
    al  = __ldg(g + (cc)) * rsqrtf(var + BN_EPS);                      \
    be  = __ldg(b + (cc)) - al * mu;                                   \
    v.comp = fmaf(al, v.comp, be);
    BN_COMP(x, c + 0)
    BN_COMP(y, c + 1)
    BN_COMP(z, c + 2)
    BN_COMP(w, c + 3)
#undef BN_COMP
    ((float4*)a)[i] = v;
}

// ---------------------------------------------------------------------------
extern "C" void kernel_launch(void* const* d_in, const int* in_sizes, int n_in,
                              void* d_out, int out_size)
{
    const float* x  = (const float*)d_in[0];
    const int* src  = (const int*)d_in[1];
    const int* dst  = (const int*)d_in[2];
    int n = in_sizes[0] / 64;
    int e = in_sizes[1];
    float invN = 1.0f / (float)n;

    void *p;
    cudaGetSymbolAddress(&p, g_agg);   float* agg  = (float*)p;
    cudaGetSymbolAddress(&p, g_bufA);  float* bufA = (float*)p;
    cudaGetSymbolAddress(&p, g_bufB);  float* bufB = (float*)p;
    cudaGetSymbolAddress(&p, g_stats1); float* s1  = (float*)p;
    cudaGetSymbolAddress(&p, g_stats2); float* s2  = (float*)p;

    int mmGrid   = (n + 255) / 256;
    int fnGrid   = (n + 127) / 128;
    int scGrid   = ((long)e * 16 + 255) / 256;
    int stGrid   = 592;                 // 592*256 threads, multiple of 64
    int bnGrid   = (n * 16 + 255) / 256;
    long total   = (long)n * 64;

    for (int layer = 0; layer < 3; layer++) {
        const float* h_in = (layer == 0) ? x : bufB;
        const float* W1 = (const float*)d_in[3 + layer * 6 + 0];
        const float* b1 = (const float*)d_in[3 + layer * 6 + 1];
        const float* gi = (const float*)d_in[3 + layer * 6 + 2];
        const float* bt = (const float*)d_in[3 + layer * 6 + 3];
        const float* W2 = (const float*)d_in[3 + layer * 6 + 4];
        const float* b2 = (const float*)d_in[3 + layer * 6 + 5];

        cudaMemsetAsync(agg, 0, (size_t)n * 64 * sizeof(float));
        cudaMemsetAsync(s1, 0, 2 * 64 * sizeof(float));
        cudaMemsetAsync(s2, 0, 2 * 64 * sizeof(float));

        scatter_kernel<<<scGrid, 256>>>(h_in, src, dst, agg, e);
        mm1_kernel<<<mmGrid, 256>>>(h_in, agg, W1, b1, bufA, n);
        colstats_kernel<<<stGrid, 256>>>(bufA, s1, total);

        if (layer < 2) {
            mm2_mid_kernel<<<mmGrid, 256>>>(bufA, s1, gi, bt, W2, b2, bufB, n, invN);
            colstats_kernel<<<stGrid, 256>>>(bufB, s2, total);
            const float* bg = (const float*)d_in[21 + layer * 2];
            const float* bb = (const float*)d_in[22 + layer * 2];
            bn_apply_kernel<<<bnGrid, 256>>>(bufB, s2, bg, bb, n, invN);
        } else {
            mm2_final_kernel<<<fnGrid, 128>>>(bufA, s1, gi, bt, W2, b2,
                                              (float*)d_out, n, invN);
        }
    }
}

// round 3
// speedup vs baseline: 1.3701x; 1.3701x over previous
#include <cuda_runtime.h>
#include <math.h>

#define NN   100000
#define EEDG 1600000
#define HIDW 64
#define OUTW 40
#define BN_EPS 1e-5f
#define SCAN_TILE 1024
#define SCAN_BLKS ((NN + SCAN_TILE - 1) / SCAN_TILE)

// Scratch (static device globals; allocation is forbidden)
__device__ __align__(16) float g_r   [NN * HIDW];   // fused h+agg buffer
__device__ __align__(16) float g_bufA[NN * HIDW];
__device__ __align__(16) float g_bufB[NN * HIDW];
__device__ float g_stats1[2 * HIDW];
__device__ float g_stats2[2 * HIDW];
__device__ int   g_deg[NN];
__device__ int   g_off[NN];
__device__ int   g_cursor[NN];
__device__ int   g_partial[SCAN_BLKS];
__device__ int   g_esrc[EEDG];

// ---------------------------------------------------------------------------
// CSR build: histogram of dst
// ---------------------------------------------------------------------------
__global__ __launch_bounds__(256) void hist_kernel(
    const int* __restrict__ dst, int* __restrict__ deg, int nE)
{
    int stride = gridDim.x * 256;
    for (int e = blockIdx.x * 256 + threadIdx.x; e < nE; e += stride)
        atomicAdd(&deg[__ldg(dst + e)], 1);
}

__global__ __launch_bounds__(SCAN_TILE) void scan1_kernel(
    const int* __restrict__ deg, int* __restrict__ partial, int n)
{
    __shared__ int sh[SCAN_TILE];
    int i = blockIdx.x * SCAN_TILE + threadIdx.x;
    sh[threadIdx.x] = (i < n) ? deg[i] : 0;
    __syncthreads();
    for (int s = SCAN_TILE / 2; s > 0; s >>= 1) {
        if (threadIdx.x < s) sh[threadIdx.x] += sh[threadIdx.x + s];
        __syncthreads();
    }
    if (threadIdx.x == 0) partial[blockIdx.x] = sh[0];
}

__global__ void scan2_kernel(int* __restrict__ partial, int nb)
{
    if (threadIdx.x == 0) {
        int run = 0;
        for (int b = 0; b < nb; b++) {
            int v = partial[b];
            partial[b] = run;
            run += v;
        }
    }
}

__global__ __launch_bounds__(SCAN_TILE) void scan3_kernel(
    const int* __restrict__ deg, const int* __restrict__ partial,
    int* __restrict__ off, int* __restrict__ cursor, int n)
{
    __shared__ int sh[SCAN_TILE];
    int i = blockIdx.x * SCAN_TILE + threadIdx.x;
    int v = (i < n) ? deg[i] : 0;
    sh[threadIdx.x] = v;
    __syncthreads();
    int val = v;
    for (int s = 1; s < SCAN_TILE; s <<= 1) {
        int add = (threadIdx.x >= s) ? sh[threadIdx.x - s] : 0;
        __syncthreads();
        val += add;
        sh[threadIdx.x] = val;
        __syncthreads();
    }
    if (i < n) {
        int o = partial[blockIdx.x] + val - v;   // exclusive prefix
        off[i] = o;
        cursor[i] = o;
    }
}

__global__ __launch_bounds__(256) void place_kernel(
    const int* __restrict__ src, const int* __restrict__ dst,
    int* __restrict__ cursor, int* __restrict__ esrc, int nE)
{
    int stride = gridDim.x * 256;
    for (int e = blockIdx.x * 256 + threadIdx.x; e < nE; e += stride) {
        int pos = atomicAdd(&cursor[__ldg(dst + e)], 1);
        esrc[pos] = __ldg(src + e);
    }
}

// ---------------------------------------------------------------------------
// Gather aggregation + residual: r[v] = h[v] + sum_{e: dst=v} h[src_e]
// 16 threads per node; each thread owns one float4 column chunk.
// ---------------------------------------------------------------------------
__global__ __launch_bounds__(256) void gather_r_kernel(
    const float* __restrict__ h, const int* __restrict__ esrc,
    const int* __restrict__ off, const int* __restrict__ deg,
    float* __restrict__ r, int n)
{
    int t = blockIdx.x * 256 + threadIdx.x;
    int v = t >> 4;
    if (v >= n) return;
    int c = t & 15;
    int o = __ldg(off + v);
    int d = __ldg(deg + v);
    float4 acc = __ldg((const float4*)h + (size_t)v * 16 + c);
    const int* ep = esrc + o;
#pragma unroll 4
    for (int j = 0; j < d; j++) {
        int s = __ldg(ep + j);
        float4 x = __ldg((const float4*)h + (size_t)s * 16 + c);
        acc.x += x.x; acc.y += x.y; acc.z += x.z; acc.w += x.w;
    }
    ((float4*)r)[(size_t)v * 16 + c] = acc;
}

// ---------------------------------------------------------------------------
// mm1: y = r @ W1 + b1     (64 -> 64)
// ---------------------------------------------------------------------------
__global__ __launch_bounds__(256, 2) void mm1_kernel(
    const float* __restrict__ rbuf,
    const float* __restrict__ W, const float* __restrict__ bias,
    float* __restrict__ y, int n)
{
    __shared__ float Ws[64 * 64];
    for (int i = threadIdx.x; i < 64 * 64; i += 256) Ws[i] = W[i];
    __syncthreads();
    int node = blockIdx.x * 256 + threadIdx.x;
    if (node >= n) return;

    float r[64];
    const float4* r4 = (const float4*)rbuf + (size_t)node * 16;
#pragma unroll
    for (int k4 = 0; k4 < 16; k4++) {
        float4 v = __ldg(r4 + k4);
        r[4*k4+0] = v.x; r[4*k4+1] = v.y; r[4*k4+2] = v.z; r[4*k4+3] = v.w;
    }
    float4* yo = (float4*)y + (size_t)node * 16;
    const float4* b4 = (const float4*)bias;
    const float4* W4 = (const float4*)Ws;
    for (int j4 = 0; j4 < 16; j4++) {
        float4 acc = b4[j4];
#pragma unroll
        for (int k = 0; k < 64; k++) {
            float4 w = W4[k * 16 + j4];
            acc.x = fmaf(r[k], w.x, acc.x);
            acc.y = fmaf(r[k], w.y, acc.y);
            acc.z = fmaf(r[k], w.z, acc.z);
            acc.w = fmaf(r[k], w.w, acc.w);
        }
        yo[j4] = acc;
    }
}

// ---------------------------------------------------------------------------
// Column stats: stats[0:64] += colsum, stats[64:128] += colsumsq
// ---------------------------------------------------------------------------
__global__ __launch_bounds__(256) void colstats_kernel(
    const float* __restrict__ v, float* __restrict__ stats, long total)
{
    float s = 0.f, sq = 0.f;
    long stride = (long)gridDim.x * 256;
    for (long i = (long)blockIdx.x * 256 + threadIdx.x; i < total; i += stride) {
        float x = v[i];
        s += x; sq += x * x;
    }
    __shared__ float sh[512];
    sh[threadIdx.x] = s;
    sh[256 + threadIdx.x] = sq;
    __syncthreads();
    if (threadIdx.x < 64) {
        float ts = 0.f, tq = 0.f;
#pragma unroll
        for (int r = 0; r < 256; r += 64) {
            ts += sh[threadIdx.x + r];
            tq += sh[256 + threadIdx.x + r];
        }
        atomicAdd(&stats[threadIdx.x], ts);
        atomicAdd(&stats[64 + threadIdx.x], tq);
    }
}

// ---------------------------------------------------------------------------
// mm2 (mid layers): h1 = relu(BN(y)) ; z = h1 @ W2 + b2 ; a = relu(z)
// ---------------------------------------------------------------------------
__global__ __launch_bounds__(256, 2) void mm2_mid_kernel(
    const float* __restrict__ y, const float* __restrict__ stats,
    const float* __restrict__ g, const float* __restrict__ bt,
    const float* __restrict__ W, const float* __restrict__ bias,
    float* __restrict__ a_out, int n, float invN)
{
    __shared__ float Ws[64 * 64];
    __shared__ float alpha[64], beta[64];
    for (int i = threadIdx.x; i < 64 * 64; i += 256) Ws[i] = W[i];
    if (threadIdx.x < 64) {
        int c = threadIdx.x;
        float mu  = stats[c] * invN;
        float var = stats[64 + c] * invN - mu * mu;
        float al  = g[c] * rsqrtf(var + BN_EPS);
        alpha[c] = al;
        beta[c]  = bt[c] - al * mu;
    }
    __syncthreads();
    int node = blockIdx.x * 256 + threadIdx.x;
    if (node >= n) return;

    float r[64];
    const float4* y4 = (const float4*)y + (size_t)node * 16;
#pragma unroll
    for (int k4 = 0; k4 < 16; k4++) {
        float4 v = __ldg(y4 + k4);
        int k = 4 * k4;
        r[k+0] = fmaxf(fmaf(alpha[k+0], v.x, beta[k+0]), 0.f);
        r[k+1] = fmaxf(fmaf(alpha[k+1], v.y, beta[k+1]), 0.f);
        r[k+2] = fmaxf(fmaf(alpha[k+2], v.z, beta[k+2]), 0.f);
        r[k+3] = fmaxf(fmaf(alpha[k+3], v.w, beta[k+3]), 0.f);
    }
    float4* ao = (float4*)a_out + (size_t)node * 16;
    const float4* b4 = (const float4*)bias;
    const float4* W4 = (const float4*)Ws;
    for (int j4 = 0; j4 < 16; j4++) {
        float4 acc = b4[j4];
#pragma unroll
        for (int k = 0; k < 64; k++) {
            float4 w = W4[k * 16 + j4];
            acc.x = fmaf(r[k], w.x, acc.x);
            acc.y = fmaf(r[k], w.y, acc.y);
            acc.z = fmaf(r[k], w.z, acc.z);
            acc.w = fmaf(r[k], w.w, acc.w);
        }
        acc.x = fmaxf(acc.x, 0.f); acc.y = fmaxf(acc.y, 0.f);
        acc.z = fmaxf(acc.z, 0.f); acc.w = fmaxf(acc.w, 0.f);
        ao[j4] = acc;
    }
}

// ---------------------------------------------------------------------------
// mm2 final: h1 = relu(BN(y)) ; z = h1 @ W2 + b2 (64->40) ; out = log_softmax(z)
// ---------------------------------------------------------------------------
__global__ __launch_bounds__(128, 3) void mm2_final_kernel(
    const float* __restrict__ y, const float* __restrict__ stats,
    const float* __restrict__ g, const float* __restrict__ bt,
    const float* __restrict__ W, const float* __restrict__ bias,
    float* __restrict__ out, int n, float invN)
{
    __shared__ float Ws[64 * 40];
    __shared__ float alpha[64], beta[64];
    for (int i = threadIdx.x; i < 64 * 40; i += 128) Ws[i] = W[i];
    if (threadIdx.x < 64) {
        int c = threadIdx.x;
        float mu  = stats[c] * invN;
        float var = stats[64 + c] * invN - mu * mu;
        float al  = g[c] * rsqrtf(var + BN_EPS);
        alpha[c] = al;
        beta[c]  = bt[c] - al * mu;
    }
    __syncthreads();
    int node = blockIdx.x * 128 + threadIdx.x;
    if (node >= n) return;

    float r[64];
    const float4* y4 = (const float4*)y + (size_t)node * 16;
#pragma unroll
    for (int k4 = 0; k4 < 16; k4++) {
        float4 v = __ldg(y4 + k4);
        int k = 4 * k4;
        r[k+0] = fmaxf(fmaf(alpha[k+0], v.x, beta[k+0]), 0.f);
        r[k+1] = fmaxf(fmaf(alpha[k+1], v.y, beta[k+1]), 0.f);
        r[k+2] = fmaxf(fmaf(alpha[k+2], v.z, beta[k+2]), 0.f);
        r[k+3] = fmaxf(fmaf(alpha[k+3], v.w, beta[k+3]), 0.f);
    }
    float z[40];
    const float4* b4 = (const float4*)bias;
    const float4* W4 = (const float4*)Ws;
    for (int j4 = 0; j4 < 10; j4++) {
        float4 acc = b4[j4];
#pragma unroll
        for (int k = 0; k < 64; k++) {
            float4 w = W4[k * 10 + j4];
            acc.x = fmaf(r[k], w.x, acc.x);
            acc.y = fmaf(r[k], w.y, acc.y);
            acc.z = fmaf(r[k], w.z, acc.z);
            acc.w = fmaf(r[k], w.w, acc.w);
        }
        z[4*j4+0] = acc.x; z[4*j4+1] = acc.y;
        z[4*j4+2] = acc.z; z[4*j4+3] = acc.w;
    }
    float m = z[0];
#pragma unroll
    for (int j = 1; j < 40; j++) m = fmaxf(m, z[j]);
    float s = 0.f;
#pragma unroll
    for (int j = 0; j < 40; j++) s += expf(z[j] - m);
    float lse = m + logf(s);
    float4* o4 = (float4*)out + (size_t)node * 10;
    for (int j4 = 0; j4 < 10; j4++) {
        float4 v;
        v.x = z[4*j4+0] - lse; v.y = z[4*j4+1] - lse;
        v.z = z[4*j4+2] - lse; v.w = z[4*j4+3] - lse;
        o4[j4] = v;
    }
}

// ---------------------------------------------------------------------------
// Outer BN apply (in place)
// ---------------------------------------------------------------------------
__global__ __launch_bounds__(256) void bn_apply_kernel(
    float* __restrict__ a, const float* __restrict__ stats,
    const float* __restrict__ g, const float* __restrict__ b,
    int n, float invN)
{
    int i = blockIdx.x * 256 + threadIdx.x;
    if (i >= n * 16) return;
    int c = (i & 15) * 4;
    float4 v = ((float4*)a)[i];
    float al, be, mu, var;
#define BN_COMP(comp, cc)                                              \
    mu  = __ldg(stats + (cc)) * invN;                                  \
    var = __ldg(stats + 64 + (cc)) * invN - mu * mu;                   \
    al  = __ldg(g + (cc)) * rsqrtf(var + BN_EPS);                      \
    be  = __ldg(b + (cc)) - al * mu;                                   \
    v.comp = fmaf(al, v.comp, be);
    BN_COMP(x, c + 0)
    BN_COMP(y, c + 1)
    BN_COMP(z, c + 2)
    BN_COMP(w, c + 3)
#undef BN_COMP
    ((float4*)a)[i] = v;
}

// ---------------------------------------------------------------------------
extern "C" void kernel_launch(void* const* d_in, const int* in_sizes, int n_in,
                              void* d_out, int out_size)
{
    const float* x  = (const float*)d_in[0];
    const int* src  = (const int*)d_in[1];
    const int* dst  = (const int*)d_in[2];
    int n = in_sizes[0] / 64;
    int e = in_sizes[1];
    float invN = 1.0f / (float)n;

    void *p;
    cudaGetSymbolAddress(&p, g_r);      float* rbuf = (float*)p;
    cudaGetSymbolAddress(&p, g_bufA);   float* bufA = (float*)p;
    cudaGetSymbolAddress(&p, g_bufB);   float* bufB = (float*)p;
    cudaGetSymbolAddress(&p, g_stats1); float* s1   = (float*)p;
    cudaGetSymbolAddress(&p, g_stats2); float* s2   = (float*)p;
    cudaGetSymbolAddress(&p, g_deg);     int* deg    = (int*)p;
    cudaGetSymbolAddress(&p, g_off);     int* off    = (int*)p;
    cudaGetSymbolAddress(&p, g_cursor);  int* cursor = (int*)p;
    cudaGetSymbolAddress(&p, g_partial); int* part   = (int*)p;
    cudaGetSymbolAddress(&p, g_esrc);    int* esrc   = (int*)p;

    int scanBlks = (n + SCAN_TILE - 1) / SCAN_TILE;
    int mmGrid   = (n + 255) / 256;
    int fnGrid   = (n + 127) / 128;
    int gaGrid   = ((long)n * 16 + 255) / 256;
    int stGrid   = 592;
    int bnGrid   = (n * 16 + 255) / 256;
    long total   = (long)n * 64;

    // ---- Build CSR by dst (once; reused for all 3 layers) ----
    cudaMemsetAsync(deg, 0, n * sizeof(int));
    hist_kernel<<<1184, 256>>>(dst, deg, e);
    scan1_kernel<<<scanBlks, SCAN_TILE>>>(deg, part, n);
    scan2_kernel<<<1, 32>>>(part, scanBlks);
    scan3_kernel<<<scanBlks, SCAN_TILE>>>(deg, part, off, cursor, n);
    place_kernel<<<1184, 256>>>(src, dst, cursor, esrc, e);

    for (int layer = 0; layer < 3; layer++) {
        const float* h_in = (layer == 0) ? x : bufB;
        const float* W1 = (const float*)d_in[3 + layer * 6 + 0];
        const float* b1 = (const float*)d_in[3 + layer * 6 + 1];
        const float* gi = (const float*)d_in[3 + layer * 6 + 2];
        const float* bt = (const float*)d_in[3 + layer * 6 + 3];
        const float* W2 = (const float*)d_in[3 + layer * 6 + 4];
        const float* b2 = (const float*)d_in[3 + layer * 6 + 5];

        cudaMemsetAsync(s1, 0, 2 * 64 * sizeof(float));
        cudaMemsetAsync(s2, 0, 2 * 64 * sizeof(float));

        gather_r_kernel<<<gaGrid, 256>>>(h_in, esrc, off, deg, rbuf, n);
        mm1_kernel<<<mmGrid, 256>>>(rbuf, W1, b1, bufA, n);
        colstats_kernel<<<stGrid, 256>>>(bufA, s1, total);

        if (layer < 2) {
            mm2_mid_kernel<<<mmGrid, 256>>>(bufA, s1, gi, bt, W2, b2, bufB, n, invN);
            colstats_kernel<<<stGrid, 256>>>(bufB, s2, total);
            const float* bg = (const float*)d_in[21 + layer * 2];
            const float* bb = (const float*)d_in[22 + layer * 2];
            bn_apply_kernel<<<bnGrid, 256>>>(bufB, s2, bg, bb, n, invN);
        } else {
            mm2_final_kernel<<<fnGrid, 128>>>(bufA, s1, gi, bt, W2, b2,
                                              (float*)d_out, n, invN);
        }
    }
}

// round 5
// speedup vs baseline: 1.8178x; 1.3268x over previous
#include <cuda_runtime.h>
#include <math.h>

#define NN   100000
#define EEDG 1600000
#define BN_EPS 1e-5f
#define SCAN_TILE 1024
#define SCAN_BLKS ((NN + SCAN_TILE - 1) / SCAN_TILE)

#define TILE_N 96          // nodes per block tile
#define RPAD   68          // padded smem row stride (floats): 16B-aligned, conflict-free

// Scratch (static device globals; allocation is forbidden)
__device__ __align__(16) float g_bufA[NN * 64];
__device__ __align__(16) float g_bufB[NN * 64];
__device__ float g_stats[5 * 128];     // s1_0, s2_0, s1_1, s2_1, s1_2
__device__ int   g_deg[NN];
__device__ int   g_off[NN];
__device__ int   g_cursor[NN];
__device__ int   g_partial[SCAN_BLKS];
__device__ int   g_esrc[EEDG];

// ---------------------------------------------------------------------------
// CSR build
// ---------------------------------------------------------------------------
__global__ __launch_bounds__(256) void hist_kernel(
    const int* __restrict__ dst, int* __restrict__ deg, int nE)
{
    int stride = gridDim.x * 256;
    for (int e = blockIdx.x * 256 + threadIdx.x; e < nE; e += stride)
        atomicAdd(&deg[__ldg(dst + e)], 1);
}

__global__ __launch_bounds__(SCAN_TILE) void scan1_kernel(
    const int* __restrict__ deg, int* __restrict__ partial, int n)
{
    __shared__ int sh[SCAN_TILE];
    int i = blockIdx.x * SCAN_TILE + threadIdx.x;
    sh[threadIdx.x] = (i < n) ? deg[i] : 0;
    __syncthreads();
    for (int s = SCAN_TILE / 2; s > 0; s >>= 1) {
        if (threadIdx.x < s) sh[threadIdx.x] += sh[threadIdx.x + s];
        __syncthreads();
    }
    if (threadIdx.x == 0) partial[blockIdx.x] = sh[0];
}

// parallel exclusive scan of block partials (nb <= 128)
__global__ __launch_bounds__(128) void scan2_kernel(int* __restrict__ partial, int nb)
{
    __shared__ int sh[128];
    int t = threadIdx.x;
    int v = (t < nb) ? partial[t] : 0;
    sh[t] = v;
    __syncthreads();
    int val = v;
    for (int s = 1; s < 128; s <<= 1) {
        int add = (t >= s) ? sh[t - s] : 0;
        __syncthreads();
        val += add;
        sh[t] = val;
        __syncthreads();
    }
    if (t < nb) partial[t] = val - v;   // exclusive
}

__global__ __launch_bounds__(SCAN_TILE) void scan3_kernel(
    const int* __restrict__ deg, const int* __restrict__ partial,
    int* __restrict__ off, int* __restrict__ cursor, int n)
{
    __shared__ int sh[SCAN_TILE];
    int i = blockIdx.x * SCAN_TILE + threadIdx.x;
    int v = (i < n) ? deg[i] : 0;
    sh[threadIdx.x] = v;
    __syncthreads();
    int val = v;
    for (int s = 1; s < SCAN_TILE; s <<= 1) {
        int add = (threadIdx.x >= s) ? sh[threadIdx.x - s] : 0;
        __syncthreads();
        val += add;
        sh[threadIdx.x] = val;
        __syncthreads();
    }
    if (i < n) {
        int o = partial[blockIdx.x] + val - v;
        off[i] = o;
        cursor[i] = o;
    }
}

__global__ __launch_bounds__(256) void place_kernel(
    const int* __restrict__ src, const int* __restrict__ dst,
    int* __restrict__ cursor, int* __restrict__ esrc, int nE)
{
    int stride = gridDim.x * 256;
    for (int e = blockIdx.x * 256 + threadIdx.x; e < nE; e += stride) {
        int pos = atomicAdd(&cursor[__ldg(dst + e)], 1);
        esrc[pos] = __ldg(src + e);
    }
}

// ---------------------------------------------------------------------------
// Fused: [optional outer-BN affine of prev layer] + gather + mm1 + col stats
//   rs[v] = alpha (.) (h[v] + sum_src h[src]) + (deg+1) * beta     (BN_IN)
//   y     = rs @ W1 + b1 ;  stats_out += colsum/colsumsq of y
// Block: 256 threads, TILE_N=96 nodes. mm phase: 6 nodes x 4 cols per thread.
// ---------------------------------------------------------------------------
template<bool BN_IN>
__global__ __launch_bounds__(256) void gather_mm1_kernel(
    const float* __restrict__ h, const int* __restrict__ esrc,
    const int* __restrict__ off, const int* __restrict__ deg,
    const float* __restrict__ pstats, const float* __restrict__ pg,
    const float* __restrict__ pb,
    const float* __restrict__ W, const float* __restrict__ bias,
    float* __restrict__ y, float* __restrict__ stats_out,
    int n, float invN)
{
    __shared__ float rs[TILE_N * RPAD];
    __shared__ float Ws[64 * 64];
    __shared__ float alpha[64], beta[64];
    __shared__ float st_s[64], st_q[64];

    int t = threadIdx.x;
    for (int i = t; i < 64 * 64; i += 256) Ws[i] = W[i];
    if (t < 64) {
        if (BN_IN) {
            float mu  = pstats[t] * invN;
            float var = pstats[64 + t] * invN - mu * mu;
            float al  = pg[t] * rsqrtf(var + BN_EPS);
            alpha[t] = al;
            beta[t]  = pb[t] - al * mu;
        }
        st_s[t] = 0.f; st_q[t] = 0.f;
    }
    __syncthreads();

    int base = blockIdx.x * TILE_N;
    int ty = t >> 4, tx = t & 15;

    // ---- gather phase: 6 passes x 16 nodes, 16 threads per node ----
    for (int sub = 0; sub < 6; sub++) {
        int nl = sub * 16 + ty;
        int v = base + nl;
        if (v < n) {
            int o = __ldg(off + v);
            int d = __ldg(deg + v);
            float4 acc = __ldg((const float4*)h + (size_t)v * 16 + tx);
            const int* ep = esrc + o;
#pragma unroll 4
            for (int j = 0; j < d; j++) {
                int s = __ldg(ep + j);
                float4 x = __ldg((const float4*)h + (size_t)s * 16 + tx);
                acc.x += x.x; acc.y += x.y; acc.z += x.z; acc.w += x.w;
            }
            if (BN_IN) {
                float db = (float)(d + 1);
                int k = tx * 4;
                acc.x = fmaf(alpha[k+0], acc.x, db * beta[k+0]);
                acc.y = fmaf(alpha[k+1], acc.y, db * beta[k+1]);
                acc.z = fmaf(alpha[k+2], acc.z, db * beta[k+2]);
                acc.w = fmaf(alpha[k+3], acc.w, db * beta[k+3]);
            }
            *(float4*)&rs[nl * RPAD + tx * 4] = acc;
        }
    }
    __syncthreads();

    // ---- mm phase: thread computes 6 nodes x 4 cols ----
    float acc[6][4];
    float4 bv = ((const float4*)bias)[tx];
#pragma unroll
    for (int i = 0; i < 6; i++) {
        acc[i][0] = bv.x; acc[i][1] = bv.y; acc[i][2] = bv.z; acc[i][3] = bv.w;
    }
    const float* rrow = &rs[(ty * 6) * RPAD];
    const float4* W4 = (const float4*)Ws;
#pragma unroll 4
    for (int k = 0; k < 64; k++) {
        float4 w = W4[k * 16 + tx];
#pragma unroll
        for (int i = 0; i < 6; i++) {
            float rv = rrow[i * RPAD + k];
            acc[i][0] = fmaf(rv, w.x, acc[i][0]);
            acc[i][1] = fmaf(rv, w.y, acc[i][1]);
            acc[i][2] = fmaf(rv, w.z, acc[i][2]);
            acc[i][3] = fmaf(rv, w.w, acc[i][3]);
        }
    }

    // ---- store + column stats ----
    float s4[4] = {0,0,0,0}, q4[4] = {0,0,0,0};
#pragma unroll
    for (int i = 0; i < 6; i++) {
        int v = base + ty * 6 + i;
        if (v < n) {
            float4 o;
            o.x = acc[i][0]; o.y = acc[i][1]; o.z = acc[i][2]; o.w = acc[i][3];
            ((float4*)y)[(size_t)v * 16 + tx] = o;
            s4[0] += o.x; q4[0] += o.x * o.x;
            s4[1] += o.y; q4[1] += o.y * o.y;
            s4[2] += o.z; q4[2] += o.z * o.z;
            s4[3] += o.w; q4[3] += o.w * o.w;
        }
    }
#pragma unroll
    for (int cc = 0; cc < 4; cc++) {
        atomicAdd(&st_s[tx * 4 + cc], s4[cc]);
        atomicAdd(&st_q[tx * 4 + cc], q4[cc]);
    }
    __syncthreads();
    if (t < 64) {
        atomicAdd(&stats_out[t],      st_s[t]);
        atomicAdd(&stats_out[64 + t], st_q[t]);
    }
}

// ---------------------------------------------------------------------------
// Fused mid mm2: h1 = relu(BN(y)) ; z = relu(h1 @ W2 + b2) ; stats of z
// ---------------------------------------------------------------------------
__global__ __launch_bounds__(256) void mm2_mid_kernel(
    const float* __restrict__ yin, const float* __restrict__ stats,
    const float* __restrict__ g, const float* __restrict__ bt,
    const float* __restrict__ W, const float* __restrict__ bias,
    float* __restrict__ a_out, float* __restrict__ stats_out,
    int n, float invN)
{
    __shared__ float rs[TILE_N * RPAD];
    __shared__ float Ws[64 * 64];
    __shared__ float alpha[64], beta[64];
    __shared__ float st_s[64], st_q[64];

    int t = threadIdx.x;
    for (int i = t; i < 64 * 64; i += 256) Ws[i] = W[i];
    if (t < 64) {
        float mu  = stats[t] * invN;
        float var = stats[64 + t] * invN - mu * mu;
        float al  = g[t] * rsqrtf(var + BN_EPS);
        alpha[t] = al;
        beta[t]  = bt[t] - al * mu;
        st_s[t] = 0.f; st_q[t] = 0.f;
    }
    __syncthreads();

    int base = blockIdx.x * TILE_N;

    // ---- load input tile, apply BN affine + relu ----
    for (int idx = t; idx < TILE_N * 16; idx += 256) {
        int nl = idx >> 4, k4 = idx & 15;
        int v = base + nl;
        if (v < n) {
            float4 x = __ldg((const float4*)yin + (size_t)v * 16 + k4);
            int k = k4 * 4;
            x.x = fmaxf(fmaf(alpha[k+0], x.x, beta[k+0]), 0.f);
            x.y = fmaxf(fmaf(alpha[k+1], x.y, beta[k+1]), 0.f);
            x.z = fmaxf(fmaf(alpha[k+2], x.z, beta[k+2]), 0.f);
            x.w = fmaxf(fmaf(alpha[k+3], x.w, beta[k+3]), 0.f);
            *(float4*)&rs[nl * RPAD + k] = x;
        }
    }
    __syncthreads();

    int ty = t >> 4, tx = t & 15;
    float acc[6][4];
    float4 bv = ((const float4*)bias)[tx];
#pragma unroll
    for (int i = 0; i < 6; i++) {
        acc[i][0] = bv.x; acc[i][1] = bv.y; acc[i][2] = bv.z; acc[i][3] = bv.w;
    }
    const float* rrow = &rs[(ty * 6) * RPAD];
    const float4* W4 = (const float4*)Ws;
#pragma unroll 4
    for (int k = 0; k < 64; k++) {
        float4 w = W4[k * 16 + tx];
#pragma unroll
        for (int i = 0; i < 6; i++) {
            float rv = rrow[i * RPAD + k];
            acc[i][0] = fmaf(rv, w.x, acc[i][0]);
            acc[i][1] = fmaf(rv, w.y, acc[i][1]);
            acc[i][2] = fmaf(rv, w.z, acc[i][2]);
            acc[i][3] = fmaf(rv, w.w, acc[i][3]);
        }
    }

    float s4[4] = {0,0,0,0}, q4[4] = {0,0,0,0};
#pragma unroll
    for (int i = 0; i < 6; i++) {
        int v = base + ty * 6 + i;
        if (v < n) {
            float4 o;
            o.x = fmaxf(acc[i][0], 0.f); o.y = fmaxf(acc[i][1], 0.f);
            o.z = fmaxf(acc[i][2], 0.f); o.w = fmaxf(acc[i][3], 0.f);
            ((float4*)a_out)[(size_t)v * 16 + tx] = o;
            s4[0] += o.x; q4[0] += o.x * o.x;
            s4[1] += o.y; q4[1] += o.y * o.y;
            s4[2] += o.z; q4[2] += o.z * o.z;
            s4[3] += o.w; q4[3] += o.w * o.w;
        }
    }
#pragma unroll
    for (int cc = 0; cc < 4; cc++) {
        atomicAdd(&st_s[tx * 4 + cc], s4[cc]);
        atomicAdd(&st_q[tx * 4 + cc], q4[cc]);
    }
    __syncthreads();
    if (t < 64) {
        atomicAdd(&stats_out[t],      st_s[t]);
        atomicAdd(&stats_out[64 + t], st_q[t]);
    }
}

// ---------------------------------------------------------------------------
// mm2 final: h1 = relu(BN(y)) ; z = h1 @ W2 + b2 (64->40) ; out = log_softmax(z)
// ---------------------------------------------------------------------------
__global__ __launch_bounds__(128, 3) void mm2_final_kernel(
    const float* __restrict__ y, const float* __restrict__ stats,
    const float* __restrict__ g, const float* __restrict__ bt,
    const float* __restrict__ W, const float* __restrict__ bias,
    float* __restrict__ out, int n, float invN)
{
    __shared__ float Ws[64 * 40];
    __shared__ float alpha[64], beta[64];
    for (int i = threadIdx.x; i < 64 * 40; i += 128) Ws[i] = W[i];
    if (threadIdx.x < 64) {
        int c = threadIdx.x;
        float mu  = stats[c] * invN;
        float var = stats[64 + c] * invN - mu * mu;
        float al  = g[c] * rsqrtf(var + BN_EPS);
        alpha[c] = al;
        beta[c]  = bt[c] - al * mu;
    }
    __syncthreads();
    int node = blockIdx.x * 128 + threadIdx.x;
    if (node >= n) return;

    float r[64];
    const float4* y4 = (const float4*)y + (size_t)node * 16;
#pragma unroll
    for (int k4 = 0; k4 < 16; k4++) {
        float4 v = __ldg(y4 + k4);
        int k = 4 * k4;
        r[k+0] = fmaxf(fmaf(alpha[k+0], v.x, beta[k+0]), 0.f);
        r[k+1] = fmaxf(fmaf(alpha[k+1], v.y, beta[k+1]), 0.f);
        r[k+2] = fmaxf(fmaf(alpha[k+2], v.z, beta[k+2]), 0.f);
        r[k+3] = fmaxf(fmaf(alpha[k+3], v.w, beta[k+3]), 0.f);
    }
    float z[40];
    const float4* b4 = (const float4*)bias;
    const float4* W4 = (const float4*)Ws;
    for (int j4 = 0; j4 < 10; j4++) {
        float4 acc = b4[j4];
#pragma unroll
        for (int k = 0; k < 64; k++) {
            float4 w = W4[k * 10 + j4];
            acc.x = fmaf(r[k], w.x, acc.x);
            acc.y = fmaf(r[k], w.y, acc.y);
            acc.z = fmaf(r[k], w.z, acc.z);
            acc.w = fmaf(r[k], w.w, acc.w);
        }
        z[4*j4+0] = acc.x; z[4*j4+1] = acc.y;
        z[4*j4+2] = acc.z; z[4*j4+3] = acc.w;
    }
    float m = z[0];
#pragma unroll
    for (int j = 1; j < 40; j++) m = fmaxf(m, z[j]);
    float s = 0.f;
#pragma unroll
    for (int j = 0; j < 40; j++) s += expf(z[j] - m);
    float lse = m + logf(s);
    float4* o4 = (float4*)out + (size_t)node * 10;
    for (int j4 = 0; j4 < 10; j4++) {
        float4 v;
        v.x = z[4*j4+0] - lse; v.y = z[4*j4+1] - lse;
        v.z = z[4*j4+2] - lse; v.w = z[4*j4+3] - lse;
        o4[j4] = v;
    }
}

// ---------------------------------------------------------------------------
extern "C" void kernel_launch(void* const* d_in, const int* in_sizes, int n_in,
                              void* d_out, int out_size)
{
    const float* x  = (const float*)d_in[0];
    const int* src  = (const int*)d_in[1];
    const int* dst  = (const int*)d_in[2];
    int n = in_sizes[0] / 64;
    int e = in_sizes[1];
    float invN = 1.0f / (float)n;

    void *p;
    cudaGetSymbolAddress(&p, g_bufA);   float* bufA = (float*)p;
    cudaGetSymbolAddress(&p, g_bufB);   float* bufB = (float*)p;
    cudaGetSymbolAddress(&p, g_stats);  float* st   = (float*)p;
    cudaGetSymbolAddress(&p, g_deg);     int* deg    = (int*)p;
    cudaGetSymbolAddress(&p, g_off);     int* off    = (int*)p;
    cudaGetSymbolAddress(&p, g_cursor);  int* cursor = (int*)p;
    cudaGetSymbolAddress(&p, g_partial); int* part   = (int*)p;
    cudaGetSymbolAddress(&p, g_esrc);    int* esrc   = (int*)p;

    float* s1_0 = st;        float* s2_0 = st + 128;
    float* s1_1 = st + 256;  float* s2_1 = st + 384;
    float* s1_2 = st + 512;

    int scanBlks = (n + SCAN_TILE - 1) / SCAN_TILE;
    int tGrid = (n + TILE_N - 1) / TILE_N;
    int fnGrid = (n + 127) / 128;

    cudaMemsetAsync(st, 0, 5 * 128 * sizeof(float));
    cudaMemsetAsync(deg, 0, n * sizeof(int));
    hist_kernel<<<1184, 256>>>(dst, deg, e);
    scan1_kernel<<<scanBlks, SCAN_TILE>>>(deg, part, n);
    scan2_kernel<<<1, 128>>>(part, scanBlks);
    scan3_kernel<<<scanBlks, SCAN_TILE>>>(deg, part, off, cursor, n);
    place_kernel<<<1184, 256>>>(src, dst, cursor, esrc, e);

    // Layer 0
    gather_mm1_kernel<false><<<tGrid, 256>>>(
        x, esrc, off, deg, nullptr, nullptr, nullptr,
        (const float*)d_in[3], (const float*)d_in[4], bufA, s1_0, n, invN);
    mm2_mid_kernel<<<tGrid, 256>>>(
        bufA, s1_0, (const float*)d_in[5], (const float*)d_in[6],
        (const float*)d_in[7], (const float*)d_in[8], bufB, s2_0, n, invN);

    // Layer 1 (gather applies outer BN0 of relu'd bufB)
    gather_mm1_kernel<true><<<tGrid, 256>>>(
        bufB, esrc, off, deg, s2_0,
        (const float*)d_in[21], (const float*)d_in[22],
        (const float*)d_in[9], (const float*)d_in[10], bufA, s1_1, n, invN);
    mm2_mid_kernel<<<tGrid, 256>>>(
        bufA, s1_1, (const float*)d_in[11], (const float*)d_in[12],
        (const float*)d_in[13], (const float*)d_in[14], bufB, s2_1, n, invN);

    // Layer 2 (gather applies outer BN1)
    gather_mm1_kernel<true><<<tGrid, 256>>>(
        bufB, esrc, off, deg, s2_1,
        (const float*)d_in[23], (const float*)d_in[24],
        (const float*)d_in[15], (const float*)d_in[16], bufA, s1_2, n, invN);
    mm2_final_kernel<<<fnGrid, 128>>>(
        bufA, s1_2, (const float*)d_in[17], (const float*)d_in[18],
        (const float*)d_in[19], (const float*)d_in[20],
        (float*)d_out, n, invN);
}

// round 7
// speedup vs baseline: 1.8989x; 1.0446x over previous
#include <cuda_runtime.h>
#include <math.h>

#define NN   100000
#define EEDG 1600000
#define BN_EPS 1e-5f
#define SCAN_TILE 1024
#define SCAN_BLKS ((NN + SCAN_TILE - 1) / SCAN_TILE)

#define TILE_N 96          // nodes per block tile
#define RPAD   68          // padded smem row stride (floats)

typedef unsigned long long u64;

// packed fp32x2 helpers (Blackwell FFMA2 — only reachable via explicit PTX)
__device__ __forceinline__ u64 ffma2(u64 a, u64 b, u64 c) {
    u64 d;
    asm("fma.rn.f32x2 %0, %1, %2, %3;" : "=l"(d) : "l"(a), "l"(b), "l"(c));
    return d;
}
__device__ __forceinline__ u64 pack2(float x, float y) {
    u64 d;
    asm("mov.b64 %0, {%1, %2};" : "=l"(d) : "f"(x), "f"(y));
    return d;
}
__device__ __forceinline__ float2 unpack2(u64 v) {
    float2 r;
    asm("mov.b64 {%0, %1}, %2;" : "=f"(r.x), "=f"(r.y) : "l"(v));
    return r;
}

// Scratch (static device globals; allocation is forbidden)
__device__ __align__(16) float g_bufA[NN * 64];
__device__ __align__(16) float g_bufB[NN * 64];
__device__ float g_stats[5 * 128];
__device__ int   g_deg[NN];
__device__ int   g_off[NN];
__device__ int   g_cursor[NN];
__device__ int   g_partial[SCAN_BLKS];
__device__ int   g_esrc[EEDG];

// ---------------------------------------------------------------------------
// CSR build
// ---------------------------------------------------------------------------
__global__ __launch_bounds__(256) void hist_kernel(
    const int* __restrict__ dst, int* __restrict__ deg, int nE)
{
    int stride = gridDim.x * 256;
    for (int e = blockIdx.x * 256 + threadIdx.x; e < nE; e += stride)
        atomicAdd(&deg[__ldg(dst + e)], 1);
}

__global__ __launch_bounds__(SCAN_TILE) void scan1_kernel(
    const int* __restrict__ deg, int* __restrict__ partial, int n)
{
    __shared__ int sh[SCAN_TILE];
    int i = blockIdx.x * SCAN_TILE + threadIdx.x;
    sh[threadIdx.x] = (i < n) ? deg[i] : 0;
    __syncthreads();
    for (int s = SCAN_TILE / 2; s > 0; s >>= 1) {
        if (threadIdx.x < s) sh[threadIdx.x] += sh[threadIdx.x + s];
        __syncthreads();
    }
    if (threadIdx.x == 0) partial[blockIdx.x] = sh[0];
}

__global__ __launch_bounds__(128) void scan2_kernel(int* __restrict__ partial, int nb)
{
    __shared__ int sh[128];
    int t = threadIdx.x;
    int v = (t < nb) ? partial[t] : 0;
    sh[t] = v;
    __syncthreads();
    int val = v;
    for (int s = 1; s < 128; s <<= 1) {
        int add = (t >= s) ? sh[t - s] : 0;
        __syncthreads();
        val += add;
        sh[t] = val;
        __syncthreads();
    }
    if (t < nb) partial[t] = val - v;
}

__global__ __launch_bounds__(SCAN_TILE) void scan3_kernel(
    const int* __restrict__ deg, const int* __restrict__ partial,
    int* __restrict__ off, int* __restrict__ cursor, int n)
{
    __shared__ int sh[SCAN_TILE];
    int i = blockIdx.x * SCAN_TILE + threadIdx.x;
    int v = (i < n) ? deg[i] : 0;
    sh[threadIdx.x] = v;
    __syncthreads();
    int val = v;
    for (int s = 1; s < SCAN_TILE; s <<= 1) {
        int add = (threadIdx.x >= s) ? sh[threadIdx.x - s] : 0;
        __syncthreads();
        val += add;
        sh[threadIdx.x] = val;
        __syncthreads();
    }
    if (i < n) {
        int o = partial[blockIdx.x] + val - v;
        off[i] = o;
        cursor[i] = o;
    }
}

__global__ __launch_bounds__(256) void place_kernel(
    const int* __restrict__ src, const int* __restrict__ dst,
    int* __restrict__ cursor, int* __restrict__ esrc, int nE)
{
    int stride = gridDim.x * 256;
    for (int e = blockIdx.x * 256 + threadIdx.x; e < nE; e += stride) {
        int pos = atomicAdd(&cursor[__ldg(dst + e)], 1);
        esrc[pos] = __ldg(src + e);
    }
}

// ---------------------------------------------------------------------------
// Fused: [optional outer-BN affine] + gather + mm1 (FFMA2) + col stats
// ---------------------------------------------------------------------------
template<bool BN_IN>
__global__ __launch_bounds__(256) void gather_mm1_kernel(
    const float* __restrict__ h, const int* __restrict__ esrc,
    const int* __restrict__ off, const int* __restrict__ deg,
    const float* __restrict__ pstats, const float* __restrict__ pg,
    const float* __restrict__ pb,
    const float* __restrict__ W, const float* __restrict__ bias,
    float* __restrict__ y, float* __restrict__ stats_out,
    int n, float invN)
{
    __shared__ __align__(16) float rs[TILE_N * RPAD];
    __shared__ __align__(16) float Ws[64 * 64];
    __shared__ float alpha[64], beta[64];
    __shared__ float st_s[64], st_q[64];

    int t = threadIdx.x;
    for (int i = t; i < 64 * 64; i += 256) Ws[i] = W[i];
    if (t < 64) {
        if (BN_IN) {
            float mu  = pstats[t] * invN;
            float var = pstats[64 + t] * invN - mu * mu;
            float al  = pg[t] * rsqrtf(var + BN_EPS);
            alpha[t] = al;
            beta[t]  = pb[t] - al * mu;
        }
        st_s[t] = 0.f; st_q[t] = 0.f;
    }
    __syncthreads();

    int base = blockIdx.x * TILE_N;
    int ty = t >> 4, tx = t & 15;

    // ---- gather phase: 6 passes x 16 nodes, 16 threads per node ----
    for (int sub = 0; sub < 6; sub++) {
        int nl = sub * 16 + ty;
        int v = base + nl;
        if (v < n) {
            int o = __ldg(off + v);
            int d = __ldg(deg + v);
            float4 acc = __ldg((const float4*)h + (size_t)v * 16 + tx);
            const int* ep = esrc + o;
#pragma unroll 4
            for (int j = 0; j < d; j++) {
                int s = __ldg(ep + j);
                float4 x = __ldg((const float4*)h + (size_t)s * 16 + tx);
                acc.x += x.x; acc.y += x.y; acc.z += x.z; acc.w += x.w;
            }
            if (BN_IN) {
                float db = (float)(d + 1);
                int k = tx * 4;
                acc.x = fmaf(alpha[k+0], acc.x, db * beta[k+0]);
                acc.y = fmaf(alpha[k+1], acc.y, db * beta[k+1]);
                acc.z = fmaf(alpha[k+2], acc.z, db * beta[k+2]);
                acc.w = fmaf(alpha[k+3], acc.w, db * beta[k+3]);
            }
            *(float4*)&rs[nl * RPAD + tx * 4] = acc;
        }
    }
    __syncthreads();

    // ---- mm phase: 6 nodes x 4 cols per thread, packed FFMA2 ----
    u64 acc0[6], acc1[6];
    {
        ulonglong2 bb = ((const ulonglong2*)bias)[tx];
#pragma unroll
        for (int i = 0; i < 6; i++) { acc0[i] = bb.x; acc1[i] = bb.y; }
    }
    const float* rrow = &rs[(ty * 6) * RPAD];
    const ulonglong2* W2 = (const ulonglong2*)Ws;
#pragma unroll 4
    for (int k = 0; k < 64; k++) {
        ulonglong2 w2 = W2[k * 16 + tx];
#pragma unroll
        for (int i = 0; i < 6; i++) {
            float rv = rrow[i * RPAD + k];
            u64 rr = pack2(rv, rv);
            acc0[i] = ffma2(rr, w2.x, acc0[i]);
            acc1[i] = ffma2(rr, w2.y, acc1[i]);
        }
    }

    // ---- store + column stats ----
    float s4[4] = {0,0,0,0}, q4[4] = {0,0,0,0};
#pragma unroll
    for (int i = 0; i < 6; i++) {
        int v = base + ty * 6 + i;
        if (v < n) {
            float2 lo = unpack2(acc0[i]);
            float2 hi = unpack2(acc1[i]);
            float4 o;
            o.x = lo.x; o.y = lo.y; o.z = hi.x; o.w = hi.y;
            ((float4*)y)[(size_t)v * 16 + tx] = o;
            s4[0] += o.x; q4[0] += o.x * o.x;
            s4[1] += o.y; q4[1] += o.y * o.y;
            s4[2] += o.z; q4[2] += o.z * o.z;
            s4[3] += o.w; q4[3] += o.w * o.w;
        }
    }
#pragma unroll
    for (int cc = 0; cc < 4; cc++) {
        atomicAdd(&st_s[tx * 4 + cc], s4[cc]);
        atomicAdd(&st_q[tx * 4 + cc], q4[cc]);
    }
    __syncthreads();
    if (t < 64) {
        atomicAdd(&stats_out[t],      st_s[t]);
        atomicAdd(&stats_out[64 + t], st_q[t]);
    }
}

// ---------------------------------------------------------------------------
// Fused mid mm2: h1 = relu(BN(y)) ; z = relu(h1 @ W2 + b2) (FFMA2) ; stats
// ---------------------------------------------------------------------------
__global__ __launch_bounds__(256) void mm2_mid_kernel(
    const float* __restrict__ yin, const float* __restrict__ stats,
    const float* __restrict__ g, const float* __restrict__ bt,
    const float* __restrict__ W, const float* __restrict__ bias,
    float* __restrict__ a_out, float* __restrict__ stats_out,
    int n, float invN)
{
    __shared__ __align__(16) float rs[TILE_N * RPAD];
    __shared__ __align__(16) float Ws[64 * 64];
    __shared__ float alpha[64], beta[64];
    __shared__ float st_s[64], st_q[64];

    int t = threadIdx.x;
    for (int i = t; i < 64 * 64; i += 256) Ws[i] = W[i];
    if (t < 64) {
        float mu  = stats[t] * invN;
        float var = stats[64 + t] * invN - mu * mu;
        float al  = g[t] * rsqrtf(var + BN_EPS);
        alpha[t] = al;
        beta[t]  = bt[t] - al * mu;
        st_s[t] = 0.f; st_q[t] = 0.f;
    }
    __syncthreads();

    int base = blockIdx.x * TILE_N;

    for (int idx = t; idx < TILE_N * 16; idx += 256) {
        int nl = idx >> 4, k4 = idx & 15;
        int v = base + nl;
        if (v < n) {
            float4 x = __ldg((const float4*)yin + (size_t)v * 16 + k4);
            int k = k4 * 4;
            x.x = fmaxf(fmaf(alpha[k+0], x.x, beta[k+0]), 0.f);
            x.y = fmaxf(fmaf(alpha[k+1], x.y, beta[k+1]), 0.f);
            x.z = fmaxf(fmaf(alpha[k+2], x.z, beta[k+2]), 0.f);
            x.w = fmaxf(fmaf(alpha[k+3], x.w, beta[k+3]), 0.f);
            *(float4*)&rs[nl * RPAD + k] = x;
        }
    }
    __syncthreads();

    int ty = t >> 4, tx = t & 15;
    u64 acc0[6], acc1[6];
    {
        ulonglong2 bb = ((const ulonglong2*)bias)[tx];
#pragma unroll
        for (int i = 0; i < 6; i++) { acc0[i] = bb.x; acc1[i] = bb.y; }
    }
    const float* rrow = &rs[(ty * 6) * RPAD];
    const ulonglong2* W2 = (const ulonglong2*)Ws;
#pragma unroll 4
    for (int k = 0; k < 64; k++) {
        ulonglong2 w2 = W2[k * 16 + tx];
#pragma unroll
        for (int i = 0; i < 6; i++) {
            float rv = rrow[i * RPAD + k];
            u64 rr = pack2(rv, rv);
            acc0[i] = ffma2(rr, w2.x, acc0[i]);
            acc1[i] = ffma2(rr, w2.y, acc1[i]);
        }
    }

    float s4[4] = {0,0,0,0}, q4[4] = {0,0,0,0};
#pragma unroll
    for (int i = 0; i < 6; i++) {
        int v = base + ty * 6 + i;
        if (v < n) {
            float2 lo = unpack2(acc0[i]);
            float2 hi = unpack2(acc1[i]);
            float4 o;
            o.x = fmaxf(lo.x, 0.f); o.y = fmaxf(lo.y, 0.f);
            o.z = fmaxf(hi.x, 0.f); o.w = fmaxf(hi.y, 0.f);
            ((float4*)a_out)[(size_t)v * 16 + tx] = o;
            s4[0] += o.x; q4[0] += o.x * o.x;
            s4[1] += o.y; q4[1] += o.y * o.y;
            s4[2] += o.z; q4[2] += o.z * o.z;
            s4[3] += o.w; q4[3] += o.w * o.w;
        }
    }
#pragma unroll
    for (int cc = 0; cc < 4; cc++) {
        atomicAdd(&st_s[tx * 4 + cc], s4[cc]);
        atomicAdd(&st_q[tx * 4 + cc], q4[cc]);
    }
    __syncthreads();
    if (t < 64) {
        atomicAdd(&stats_out[t],      st_s[t]);
        atomicAdd(&stats_out[64 + t], st_q[t]);
    }
}

// ---------------------------------------------------------------------------
// mm2 final: h1 = relu(BN(y)) ; z = h1 @ W2 + b2 (64->40, FFMA2) ; log_softmax
// ---------------------------------------------------------------------------
__global__ __launch_bounds__(128, 3) void mm2_final_kernel(
    const float* __restrict__ y, const float* __restrict__ stats,
    const float* __restrict__ g, const float* __restrict__ bt,
    const float* __restrict__ W, const float* __restrict__ bias,
    float* __restrict__ out, int n, float invN)
{
    __shared__ __align__(16) float Ws[64 * 40];
    __shared__ float alpha[64], beta[64];
    for (int i = threadIdx.x; i < 64 * 40; i += 128) Ws[i] = W[i];
    if (threadIdx.x < 64) {
        int c = threadIdx.x;
        float mu  = stats[c] * invN;
        float var = stats[64 + c] * invN - mu * mu;
        float al  = g[c] * rsqrtf(var + BN_EPS);
        alpha[c] = al;
        beta[c]  = bt[c] - al * mu;
    }
    __syncthreads();
    int node = blockIdx.x * 128 + threadIdx.x;
    if (node >= n) return;

    float r[64];
    const float4* y4 = (const float4*)y + (size_t)node * 16;
#pragma unroll
    for (int k4 = 0; k4 < 16; k4++) {
        float4 v = __ldg(y4 + k4);
        int k = 4 * k4;
        r[k+0] = fmaxf(fmaf(alpha[k+0], v.x, beta[k+0]), 0.f);
        r[k+1] = fmaxf(fmaf(alpha[k+1], v.y, beta[k+1]), 0.f);
        r[k+2] = fmaxf(fmaf(alpha[k+2], v.z, beta[k+2]), 0.f);
        r[k+3] = fmaxf(fmaf(alpha[k+3], v.w, beta[k+3]), 0.f);
    }
    u64 zp[20];
    {
        const ulonglong2* b2 = (const ulonglong2*)bias;
#pragma unroll
        for (int j4 = 0; j4 < 10; j4++) {
            ulonglong2 bb = b2[j4];
            zp[2*j4] = bb.x; zp[2*j4+1] = bb.y;
        }
    }
    const ulonglong2* W2 = (const ulonglong2*)Ws;
#pragma unroll 4
    for (int k = 0; k < 64; k++) {
        u64 rr = pack2(r[k], r[k]);
#pragma unroll
        for (int j4 = 0; j4 < 10; j4++) {
            ulonglong2 w2 = W2[k * 10 + j4];
            zp[2*j4]   = ffma2(rr, w2.x, zp[2*j4]);
            zp[2*j4+1] = ffma2(rr, w2.y, zp[2*j4+1]);
        }
    }
    float z[40];
#pragma unroll
    for (int p = 0; p < 20; p++) {
        float2 v = unpack2(zp[p]);
        z[2*p] = v.x; z[2*p+1] = v.y;
    }
    float m = z[0];
#pragma unroll
    for (int j = 1; j < 40; j++) m = fmaxf(m, z[j]);
    float s = 0.f;
#pragma unroll
    for (int j = 0; j < 40; j++) s += expf(z[j] - m);
    float lse = m + logf(s);
    float4* o4 = (float4*)out + (size_t)node * 10;
    for (int j4 = 0; j4 < 10; j4++) {
        float4 v;
        v.x = z[4*j4+0] - lse; v.y = z[4*j4+1] - lse;
        v.z = z[4*j4+2] - lse; v.w = z[4*j4+3] - lse;
        o4[j4] = v;
    }
}

// ---------------------------------------------------------------------------
extern "C" void kernel_launch(void* const* d_in, const int* in_sizes, int n_in,
                              void* d_out, int out_size)
{
    const float* x  = (const float*)d_in[0];
    const int* src  = (const int*)d_in[1];
    const int* dst  = (const int*)d_in[2];
    int n = in_sizes[0] / 64;
    int e = in_sizes[1];
    float invN = 1.0f / (float)n;

    void *p;
    cudaGetSymbolAddress(&p, g_bufA);   float* bufA = (float*)p;
    cudaGetSymbolAddress(&p, g_bufB);   float* bufB = (float*)p;
    cudaGetSymbolAddress(&p, g_stats);  float* st   = (float*)p;
    cudaGetSymbolAddress(&p, g_deg);     int* deg    = (int*)p;
    cudaGetSymbolAddress(&p, g_off);     int* off    = (int*)p;
    cudaGetSymbolAddress(&p, g_cursor);  int* cursor = (int*)p;
    cudaGetSymbolAddress(&p, g_partial); int* part   = (int*)p;
    cudaGetSymbolAddress(&p, g_esrc);    int* esrc   = (int*)p;

    float* s1_0 = st;        float* s2_0 = st + 128;
    float* s1_1 = st + 256;  float* s2_1 = st + 384;
    float* s1_2 = st + 512;

    int scanBlks = (n + SCAN_TILE - 1) / SCAN_TILE;
    int tGrid = (n + TILE_N - 1) / TILE_N;
    int fnGrid = (n + 127) / 128;

    cudaMemsetAsync(st, 0, 5 * 128 * sizeof(float));
    cudaMemsetAsync(deg, 0, n * sizeof(int));
    hist_kernel<<<1184, 256>>>(dst, deg, e);
    scan1_kernel<<<scanBlks, SCAN_TILE>>>(deg, part, n);
    scan2_kernel<<<1, 128>>>(part, scanBlks);
    scan3_kernel<<<scanBlks, SCAN_TILE>>>(deg, part, off, cursor, n);
    place_kernel<<<1184, 256>>>(src, dst, cursor, esrc, e);

    // Layer 0
    gather_mm1_kernel<false><<<tGrid, 256>>>(
        x, esrc, off, deg, nullptr, nullptr, nullptr,
        (const float*)d_in[3], (const float*)d_in[4], bufA, s1_0, n, invN);
    mm2_mid_kernel<<<tGrid, 256>>>(
        bufA, s1_0, (const float*)d_in[5], (const float*)d_in[6],
        (const float*)d_in[7], (const float*)d_in[8], bufB, s2_0, n, invN);

    // Layer 1 (gather applies outer BN0)
    gather_mm1_kernel<true><<<tGrid, 256>>>(
        bufB, esrc, off, deg, s2_0,
        (const float*)d_in[21], (const float*)d_in[22],
        (const float*)d_in[9], (const float*)d_in[10], bufA, s1_1, n, invN);
    mm2_mid_kernel<<<tGrid, 256>>>(
        bufA, s1_1, (const float*)d_in[11], (const float*)d_in[12],
        (const float*)d_in[13], (const float*)d_in[14], bufB, s2_1, n, invN);

    // Layer 2 (gather applies outer BN1)
    gather_mm1_kernel<true><<<tGrid, 256>>>(
        bufB, esrc, off, deg, s2_1,
        (const float*)d_in[23], (const float*)d_in[24],
        (const float*)d_in[15], (const float*)d_in[16], bufA, s1_2, n, invN);
    mm2_final_kernel<<<fnGrid, 128>>>(
        bufA, s1_2, (const float*)d_in[17], (const float*)d_in[18],
        (const float*)d_in[19], (const float*)d_in[20],
        (float*)d_out, n, invN);
}

// round 9
// speedup vs baseline: 1.9431x; 1.0233x over previous
#include <cuda_runtime.h>
#include <cuda_bf16.h>
#include <math.h>

#define NN   100000
#define EEDG 1600000
#define BN_EPS 1e-5f
#define SCAN_TILE 1024
#define SCAN_BLKS ((NN + SCAN_TILE - 1) / SCAN_TILE)

#define TILE_N 96          // nodes per block tile
#define RPAD   68          // padded smem row stride (floats)

typedef unsigned long long u64;

// packed fp32x2 helpers (Blackwell FFMA2 — only reachable via explicit PTX)
__device__ __forceinline__ u64 ffma2(u64 a, u64 b, u64 c) {
    u64 d;
    asm("fma.rn.f32x2 %0, %1, %2, %3;" : "=l"(d) : "l"(a), "l"(b), "l"(c));
    return d;
}
__device__ __forceinline__ u64 pack2(float x, float y) {
    u64 d;
    asm("mov.b64 %0, {%1, %2};" : "=l"(d) : "f"(x), "f"(y));
    return d;
}
__device__ __forceinline__ float2 unpack2(u64 v) {
    float2 r;
    asm("mov.b64 {%0, %1}, %2;" : "=f"(r.x), "=f"(r.y) : "l"(v));
    return r;
}
__device__ __forceinline__ float4 b4_to_f4(uint2 u) {
    __nv_bfloat162 a = *(__nv_bfloat162*)&u.x;
    __nv_bfloat162 b = *(__nv_bfloat162*)&u.y;
    float2 fa = __bfloat1622float2(a);
    float2 fb = __bfloat1622float2(b);
    return make_float4(fa.x, fa.y, fb.x, fb.y);
}
__device__ __forceinline__ uint2 f4_to_b4(float4 v) {
    __nv_bfloat162 p0 = __floats2bfloat162_rn(v.x, v.y);
    __nv_bfloat162 p1 = __floats2bfloat162_rn(v.z, v.w);
    uint2 u;
    u.x = *(unsigned*)&p0;
    u.y = *(unsigned*)&p1;
    return u;
}

// Scratch (static device globals; allocation is forbidden)
__device__ __align__(16) float          g_bufA[NN * 64];  // mm1 outputs (fp32)
__device__ __align__(16) __nv_bfloat16  g_bufH[NN * 64];  // mm2 outputs (bf16)
__device__ float g_stats[5 * 128];
__device__ int   g_deg[NN];
__device__ int   g_off[NN];
__device__ int   g_cursor[NN];
__device__ int   g_partial[SCAN_BLKS];
__device__ int   g_esrc[EEDG];

// ---------------------------------------------------------------------------
// CSR build
// ---------------------------------------------------------------------------
__global__ __launch_bounds__(256) void hist_kernel(
    const int* __restrict__ dst, int* __restrict__ deg, int nE)
{
    int stride = gridDim.x * 256;
    for (int e = blockIdx.x * 256 + threadIdx.x; e < nE; e += stride)
        atomicAdd(&deg[__ldg(dst + e)], 1);
}

__global__ __launch_bounds__(SCAN_TILE) void scan1_kernel(
    const int* __restrict__ deg, int* __restrict__ partial, int n)
{
    __shared__ int sh[SCAN_TILE];
    int i = blockIdx.x * SCAN_TILE + threadIdx.x;
    sh[threadIdx.x] = (i < n) ? deg[i] : 0;
    __syncthreads();
    for (int s = SCAN_TILE / 2; s > 0; s >>= 1) {
        if (threadIdx.x < s) sh[threadIdx.x] += sh[threadIdx.x + s];
        __syncthreads();
    }
    if (threadIdx.x == 0) partial[blockIdx.x] = sh[0];
}

__global__ __launch_bounds__(128) void scan2_kernel(int* __restrict__ partial, int nb)
{
    __shared__ int sh[128];
    int t = threadIdx.x;
    int v = (t < nb) ? partial[t] : 0;
    sh[t] = v;
    __syncthreads();
    int val = v;
    for (int s = 1; s < 128; s <<= 1) {
        int add = (t >= s) ? sh[t - s] : 0;
        __syncthreads();
        val += add;
        sh[t] = val;
        __syncthreads();
    }
    if (t < nb) partial[t] = val - v;
}

__global__ __launch_bounds__(SCAN_TILE) void scan3_kernel(
    const int* __restrict__ deg, const int* __restrict__ partial,
    int* __restrict__ off, int* __restrict__ cursor, int n)
{
    __shared__ int sh[SCAN_TILE];
    int i = blockIdx.x * SCAN_TILE + threadIdx.x;
    int v = (i < n) ? deg[i] : 0;
    sh[threadIdx.x] = v;
    __syncthreads();
    int val = v;
    for (int s = 1; s < SCAN_TILE; s <<= 1) {
        int add = (threadIdx.x >= s) ? sh[threadIdx.x - s] : 0;
        __syncthreads();
        val += add;
        sh[threadIdx.x] = val;
        __syncthreads();
    }
    if (i < n) {
        int o = partial[blockIdx.x] + val - v;
        off[i] = o;
        cursor[i] = o;
    }
}

__global__ __launch_bounds__(256) void place_kernel(
    const int* __restrict__ src, const int* __restrict__ dst,
    int* __restrict__ cursor, int* __restrict__ esrc, int nE)
{
    int stride = gridDim.x * 256;
    for (int e = blockIdx.x * 256 + threadIdx.x; e < nE; e += stride) {
        int pos = atomicAdd(&cursor[__ldg(dst + e)], 1);
        esrc[pos] = __ldg(src + e);
    }
}

// ---------------------------------------------------------------------------
// Layer-0 fused: gather (fp32 x) + mm1 (FFMA2) + col stats
// ---------------------------------------------------------------------------
__global__ __launch_bounds__(256) void gather_mm1_f32_kernel(
    const float* __restrict__ h, const int* __restrict__ esrc,
    const int* __restrict__ off, const int* __restrict__ deg,
    const float* __restrict__ W, const float* __restrict__ bias,
    float* __restrict__ y, float* __restrict__ stats_out, int n)
{
    __shared__ __align__(16) float rs[TILE_N * RPAD];
    __shared__ __align__(16) float Ws[64 * 64];
    __shared__ float st_s[64], st_q[64];

    int t = threadIdx.x;
    for (int i = t; i < 64 * 64; i += 256) Ws[i] = W[i];
    if (t < 64) { st_s[t] = 0.f; st_q[t] = 0.f; }
    __syncthreads();

    int base = blockIdx.x * TILE_N;
    int ty = t >> 4, tx = t & 15;

    for (int sub = 0; sub < 6; sub++) {
        int nl = sub * 16 + ty;
        int v = base + nl;
        if (v < n) {
            int o = __ldg(off + v);
            int d = __ldg(deg + v);
            float4 acc = __ldg((const float4*)h + (size_t)v * 16 + tx);
            const int* ep = esrc + o;
#pragma unroll 4
            for (int j = 0; j < d; j++) {
                int s = __ldg(ep + j);
                float4 x = __ldg((const float4*)h + (size_t)s * 16 + tx);
                acc.x += x.x; acc.y += x.y; acc.z += x.z; acc.w += x.w;
            }
            *(float4*)&rs[nl * RPAD + tx * 4] = acc;
        }
    }
    __syncthreads();

    u64 acc0[6], acc1[6];
    {
        ulonglong2 bb = ((const ulonglong2*)bias)[tx];
#pragma unroll
        for (int i = 0; i < 6; i++) { acc0[i] = bb.x; acc1[i] = bb.y; }
    }
    const float* rrow = &rs[(ty * 6) * RPAD];
    const ulonglong2* W2 = (const ulonglong2*)Ws;
#pragma unroll 4
    for (int k = 0; k < 64; k++) {
        ulonglong2 w2 = W2[k * 16 + tx];
#pragma unroll
        for (int i = 0; i < 6; i++) {
            float rv = rrow[i * RPAD + k];
            u64 rr = pack2(rv, rv);
            acc0[i] = ffma2(rr, w2.x, acc0[i]);
            acc1[i] = ffma2(rr, w2.y, acc1[i]);
        }
    }

    float s4[4] = {0,0,0,0}, q4[4] = {0,0,0,0};
#pragma unroll
    for (int i = 0; i < 6; i++) {
        int v = base + ty * 6 + i;
        if (v < n) {
            float2 lo = unpack2(acc0[i]);
            float2 hi = unpack2(acc1[i]);
            float4 o;
            o.x = lo.x; o.y = lo.y; o.z = hi.x; o.w = hi.y;
            ((float4*)y)[(size_t)v * 16 + tx] = o;
            s4[0] += o.x; q4[0] += o.x * o.x;
            s4[1] += o.y; q4[1] += o.y * o.y;
            s4[2] += o.z; q4[2] += o.z * o.z;
            s4[3] += o.w; q4[3] += o.w * o.w;
        }
    }
#pragma unroll
    for (int cc = 0; cc < 4; cc++) {
        atomicAdd(&st_s[tx * 4 + cc], s4[cc]);
        atomicAdd(&st_q[tx * 4 + cc], q4[cc]);
    }
    __syncthreads();
    if (t < 64) {
        atomicAdd(&stats_out[t],      st_s[t]);
        atomicAdd(&stats_out[64 + t], st_q[t]);
    }
}

// ---------------------------------------------------------------------------
// Layers 1-2 fused: outer-BN affine + bf16 gather + mm1 (FFMA2) + col stats
//   rs[v] = alpha (.) (h[v] + sum_src h[src]) + (deg+1) * beta
// h is bf16 (post-relu, non-negative); accumulation in fp32.
// ---------------------------------------------------------------------------
__global__ __launch_bounds__(256) void gather_mm1_bf16_kernel(
    const __nv_bfloat16* __restrict__ h, const int* __restrict__ esrc,
    const int* __restrict__ off, const int* __restrict__ deg,
    const float* __restrict__ pstats, const float* __restrict__ pg,
    const float* __restrict__ pb,
    const float* __restrict__ W, const float* __restrict__ bias,
    float* __restrict__ y, float* __restrict__ stats_out,
    int n, float invN)
{
    __shared__ __align__(16) float rs[TILE_N * RPAD];
    __shared__ __align__(16) float Ws[64 * 64];
    __shared__ float alpha[64], beta[64];
    __shared__ float st_s[64], st_q[64];

    int t = threadIdx.x;
    for (int i = t; i < 64 * 64; i += 256) Ws[i] = W[i];
    if (t < 64) {
        float mu  = pstats[t] * invN;
        float var = pstats[64 + t] * invN - mu * mu;
        float al  = pg[t] * rsqrtf(var + BN_EPS);
        alpha[t] = al;
        beta[t]  = pb[t] - al * mu;
        st_s[t] = 0.f; st_q[t] = 0.f;
    }
    __syncthreads();

    int base = blockIdx.x * TILE_N;
    int ty = t >> 4, tx = t & 15;

    for (int sub = 0; sub < 6; sub++) {
        int nl = sub * 16 + ty;
        int v = base + nl;
        if (v < n) {
            int o = __ldg(off + v);
            int d = __ldg(deg + v);
            uint2 sv = __ldg((const uint2*)h + (size_t)v * 16 + tx);
            float4 acc = b4_to_f4(sv);
            const int* ep = esrc + o;
#pragma unroll 4
            for (int j = 0; j < d; j++) {
                int s = __ldg(ep + j);
                uint2 xv = __ldg((const uint2*)h + (size_t)s * 16 + tx);
                float4 x = b4_to_f4(xv);
                acc.x += x.x; acc.y += x.y; acc.z += x.z; acc.w += x.w;
            }
            float db = (float)(d + 1);
            int k = tx * 4;
            acc.x = fmaf(alpha[k+0], acc.x, db * beta[k+0]);
            acc.y = fmaf(alpha[k+1], acc.y, db * beta[k+1]);
            acc.z = fmaf(alpha[k+2], acc.z, db * beta[k+2]);
            acc.w = fmaf(alpha[k+3], acc.w, db * beta[k+3]);
            *(float4*)&rs[nl * RPAD + tx * 4] = acc;
        }
    }
    __syncthreads();

    u64 acc0[6], acc1[6];
    {
        ulonglong2 bb = ((const ulonglong2*)bias)[tx];
#pragma unroll
        for (int i = 0; i < 6; i++) { acc0[i] = bb.x; acc1[i] = bb.y; }
    }
    const float* rrow = &rs[(ty * 6) * RPAD];
    const ulonglong2* W2 = (const ulonglong2*)Ws;
#pragma unroll 4
    for (int k = 0; k < 64; k++) {
        ulonglong2 w2 = W2[k * 16 + tx];
#pragma unroll
        for (int i = 0; i < 6; i++) {
            float rv = rrow[i * RPAD + k];
            u64 rr = pack2(rv, rv);
            acc0[i] = ffma2(rr, w2.x, acc0[i]);
            acc1[i] = ffma2(rr, w2.y, acc1[i]);
        }
    }

    float s4[4] = {0,0,0,0}, q4[4] = {0,0,0,0};
#pragma unroll
    for (int i = 0; i < 6; i++) {
        int v = base + ty * 6 + i;
        if (v < n) {
            float2 lo = unpack2(acc0[i]);
            float2 hi = unpack2(acc1[i]);
            float4 o;
            o.x = lo.x; o.y = lo.y; o.z = hi.x; o.w = hi.y;
            ((float4*)y)[(size_t)v * 16 + tx] = o;
            s4[0] += o.x; q4[0] += o.x * o.x;
            s4[1] += o.y; q4[1] += o.y * o.y;
            s4[2] += o.z; q4[2] += o.z * o.z;
            s4[3] += o.w; q4[3] += o.w * o.w;
        }
    }
#pragma unroll
    for (int cc = 0; cc < 4; cc++) {
        atomicAdd(&st_s[tx * 4 + cc], s4[cc]);
        atomicAdd(&st_q[tx * 4 + cc], q4[cc]);
    }
    __syncthreads();
    if (t < 64) {
        atomicAdd(&stats_out[t],      st_s[t]);
        atomicAdd(&stats_out[64 + t], st_q[t]);
    }
}

// ---------------------------------------------------------------------------
// Fused mid mm2: h1 = relu(BN(y)) ; z = relu(h1 @ W2 + b2) (FFMA2)
// Writes bf16 output (for next layer's gather) + col stats (fp32-exact).
// ---------------------------------------------------------------------------
__global__ __launch_bounds__(256) void mm2_mid_kernel(
    const float* __restrict__ yin, const float* __restrict__ stats,
    const float* __restrict__ g, const float* __restrict__ bt,
    const float* __restrict__ W, const float* __restrict__ bias,
    __nv_bfloat16* __restrict__ a_out, float* __restrict__ stats_out,
    int n, float invN)
{
    __shared__ __align__(16) float rs[TILE_N * RPAD];
    __shared__ __align__(16) float Ws[64 * 64];
    __shared__ float alpha[64], beta[64];
    __shared__ float st_s[64], st_q[64];

    int t = threadIdx.x;
    for (int i = t; i < 64 * 64; i += 256) Ws[i] = W[i];
    if (t < 64) {
        float mu  = stats[t] * invN;
        float var = stats[64 + t] * invN - mu * mu;
        float al  = g[t] * rsqrtf(var + BN_EPS);
        alpha[t] = al;
        beta[t]  = bt[t] - al * mu;
        st_s[t] = 0.f; st_q[t] = 0.f;
    }
    __syncthreads();

    int base = blockIdx.x * TILE_N;

    for (int idx = t; idx < TILE_N * 16; idx += 256) {
        int nl = idx >> 4, k4 = idx & 15;
        int v = base + nl;
        if (v < n) {
            float4 x = __ldg((const float4*)yin + (size_t)v * 16 + k4);
            int k = k4 * 4;
            x.x = fmaxf(fmaf(alpha[k+0], x.x, beta[k+0]), 0.f);
            x.y = fmaxf(fmaf(alpha[k+1], x.y, beta[k+1]), 0.f);
            x.z = fmaxf(fmaf(alpha[k+2], x.z, beta[k+2]), 0.f);
            x.w = fmaxf(fmaf(alpha[k+3], x.w, beta[k+3]), 0.f);
            *(float4*)&rs[nl * RPAD + k] = x;
        }
    }
    __syncthreads();

    int ty = t >> 4, tx = t & 15;
    u64 acc0[6], acc1[6];
    {
        ulonglong2 bb = ((const ulonglong2*)bias)[tx];
#pragma unroll
        for (int i = 0; i < 6; i++) { acc0[i] = bb.x; acc1[i] = bb.y; }
    }
    const float* rrow = &rs[(ty * 6) * RPAD];
    const ulonglong2* W2 = (const ulonglong2*)Ws;
#pragma unroll 4
    for (int k = 0; k < 64; k++) {
        ulonglong2 w2 = W2[k * 16 + tx];
#pragma unroll
        for (int i = 0; i < 6; i++) {
            float rv = rrow[i * RPAD + k];
            u64 rr = pack2(rv, rv);
            acc0[i] = ffma2(rr, w2.x, acc0[i]);
            acc1[i] = ffma2(rr, w2.y, acc1[i]);
        }
    }

    float s4[4] = {0,0,0,0}, q4[4] = {0,0,0,0};
#pragma unroll
    for (int i = 0; i < 6; i++) {
        int v = base + ty * 6 + i;
        if (v < n) {
            float2 lo = unpack2(acc0[i]);
            float2 hi = unpack2(acc1[i]);
            float4 o;
            o.x = fmaxf(lo.x, 0.f); o.y = fmaxf(lo.y, 0.f);
            o.z = fmaxf(hi.x, 0.f); o.w = fmaxf(hi.y, 0.f);
            ((uint2*)a_out)[(size_t)v * 16 + tx] = f4_to_b4(o);
            s4[0] += o.x; q4[0] += o.x * o.x;
            s4[1] += o.y; q4[1] += o.y * o.y;
            s4[2] += o.z; q4[2] += o.z * o.z;
            s4[3] += o.w; q4[3] += o.w * o.w;
        }
    }
#pragma unroll
    for (int cc = 0; cc < 4; cc++) {
        atomicAdd(&st_s[tx * 4 + cc], s4[cc]);
        atomicAdd(&st_q[tx * 4 + cc], q4[cc]);
    }
    __syncthreads();
    if (t < 64) {
        atomicAdd(&stats_out[t],      st_s[t]);
        atomicAdd(&stats_out[64 + t], st_q[t]);
    }
}

// ---------------------------------------------------------------------------
// mm2 final: h1 = relu(BN(y)) ; z = h1 @ W2 + b2 (64->40, FFMA2) ; log_softmax
// ---------------------------------------------------------------------------
__global__ __launch_bounds__(128, 3) void mm2_final_kernel(
    const float* __restrict__ y, const float* __restrict__ stats,
    const float* __restrict__ g, const float* __restrict__ bt,
    const float* __restrict__ W, const float* __restrict__ bias,
    float* __restrict__ out, int n, float invN)
{
    __shared__ __align__(16) float Ws[64 * 40];
    __shared__ float alpha[64], beta[64];
    for (int i = threadIdx.x; i < 64 * 40; i += 128) Ws[i] = W[i];
    if (threadIdx.x < 64) {
        int c = threadIdx.x;
        float mu  = stats[c] * invN;
        float var = stats[64 + c] * invN - mu * mu;
        float al  = g[c] * rsqrtf(var + BN_EPS);
        alpha[c] = al;
        beta[c]  = bt[c] - al * mu;
    }
    __syncthreads();
    int node = blockIdx.x * 128 + threadIdx.x;
    if (node >= n) return;

    float r[64];
    const float4* y4 = (const float4*)y + (size_t)node * 16;
#pragma unroll
    for (int k4 = 0; k4 < 16; k4++) {
        float4 v = __ldg(y4 + k4);
        int k = 4 * k4;
        r[k+0] = fmaxf(fmaf(alpha[k+0], v.x, beta[k+0]), 0.f);
        r[k+1] = fmaxf(fmaf(alpha[k+1], v.y, beta[k+1]), 0.f);
        r[k+2] = fmaxf(fmaf(alpha[k+2], v.z, beta[k+2]), 0.f);
        r[k+3] = fmaxf(fmaf(alpha[k+3], v.w, beta[k+3]), 0.f);
    }
    u64 zp[20];
    {
        const ulonglong2* b2 = (const ulonglong2*)bias;
#pragma unroll
        for (int j4 = 0; j4 < 10; j4++) {
            ulonglong2 bb = b2[j4];
            zp[2*j4] = bb.x; zp[2*j4+1] = bb.y;
        }
    }
    const ulonglong2* W2 = (const ulonglong2*)Ws;
#pragma unroll 4
    for (int k = 0; k < 64; k++) {
        u64 rr = pack2(r[k], r[k]);
#pragma unroll
        for (int j4 = 0; j4 < 10; j4++) {
            ulonglong2 w2 = W2[k * 10 + j4];
            zp[2*j4]   = ffma2(rr, w2.x, zp[2*j4]);
            zp[2*j4+1] = ffma2(rr, w2.y, zp[2*j4+1]);
        }
    }
    float z[40];
#pragma unroll
    for (int p = 0; p < 20; p++) {
        float2 v = unpack2(zp[p]);
        z[2*p] = v.x; z[2*p+1] = v.y;
    }
    float m = z[0];
#pragma unroll
    for (int j = 1; j < 40; j++) m = fmaxf(m, z[j]);
    float s = 0.f;
#pragma unroll
    for (int j = 0; j < 40; j++) s += expf(z[j] - m);
    float lse = m + logf(s);
    float4* o4 = (float4*)out + (size_t)node * 10;
    for (int j4 = 0; j4 < 10; j4++) {
        float4 v;
        v.x = z[4*j4+0] - lse; v.y = z[4*j4+1] - lse;
        v.z = z[4*j4+2] - lse; v.w = z[4*j4+3] - lse;
        o4[j4] = v;
    }
}

// ---------------------------------------------------------------------------
extern "C" void kernel_launch(void* const* d_in, const int* in_sizes, int n_in,
                              void* d_out, int out_size)
{
    const float* x  = (const float*)d_in[0];
    const int* src  = (const int*)d_in[1];
    const int* dst  = (const int*)d_in[2];
    int n = in_sizes[0] / 64;
    int e = in_sizes[1];
    float invN = 1.0f / (float)n;

    void *p;
    cudaGetSymbolAddress(&p, g_bufA);   float* bufA = (float*)p;
    cudaGetSymbolAddress(&p, g_bufH);   __nv_bfloat16* bufH = (__nv_bfloat16*)p;
    cudaGetSymbolAddress(&p, g_stats);  float* st   = (float*)p;
    cudaGetSymbolAddress(&p, g_deg);     int* deg    = (int*)p;
    cudaGetSymbolAddress(&p, g_off);     int* off    = (int*)p;
    cudaGetSymbolAddress(&p, g_cursor);  int* cursor = (int*)p;
    cudaGetSymbolAddress(&p, g_partial); int* part   = (int*)p;
    cudaGetSymbolAddress(&p, g_esrc);    int* esrc   = (int*)p;

    float* s1_0 = st;        float* s2_0 = st + 128;
    float* s1_1 = st + 256;  float* s2_1 = st + 384;
    float* s1_2 = st + 512;

    int scanBlks = (n + SCAN_TILE - 1) / SCAN_TILE;
    int tGrid = (n + TILE_N - 1) / TILE_N;
    int fnGrid = (n + 127) / 128;

    cudaMemsetAsync(st, 0, 5 * 128 * sizeof(float));
    cudaMemsetAsync(deg, 0, n * sizeof(int));
    hist_kernel<<<1184, 256>>>(dst, deg, e);
    scan1_kernel<<<scanBlks, SCAN_TILE>>>(deg, part, n);
    scan2_kernel<<<1, 128>>>(part, scanBlks);
    scan3_kernel<<<scanBlks, SCAN_TILE>>>(deg, part, off, cursor, n);
    place_kernel<<<1184, 256>>>(src, dst, cursor, esrc, e);

    // Layer 0 (fp32 gather of x)
    gather_mm1_f32_kernel<<<tGrid, 256>>>(
        x, esrc, off, deg,
        (const float*)d_in[3], (const float*)d_in[4], bufA, s1_0, n);
    mm2_mid_kernel<<<tGrid, 256>>>(
        bufA, s1_0, (const float*)d_in[5], (const float*)d_in[6],
        (const float*)d_in[7], (const float*)d_in[8], bufH, s2_0, n, invN);

    // Layer 1 (bf16 gather + outer BN0)
    gather_mm1_bf16_kernel<<<tGrid, 256>>>(
        bufH, esrc, off, deg, s2_0,
        (const float*)d_in[21], (const float*)d_in[22],
        (const float*)d_in[9], (const float*)d_in[10], bufA, s1_1, n, invN);
    mm2_mid_kernel<<<tGrid, 256>>>(
        bufA, s1_1, (const float*)d_in[11], (const float*)d_in[12],
        (const float*)d_in[13], (const float*)d_in[14], bufH, s2_1, n, invN);

    // Layer 2 (bf16 gather + outer BN1)
    gather_mm1_bf16_kernel<<<tGrid, 256>>>(
        bufH, esrc, off, deg, s2_1,
        (const float*)d_in[23], (const float*)d_in[24],
        (const float*)d_in[15], (const float*)d_in[16], bufA, s1_2, n, invN);
    mm2_final_kernel<<<fnGrid, 128>>>(
        bufA, s1_2, (const float*)d_in[17], (const float*)d_in[18],
        (const float*)d_in[19], (const float*)d_in[20],
        (float*)d_out, n, invN);
}